// round 13
// baseline (speedup 1.0000x reference)
#include <cuda_runtime.h>
#include <math.h>

#define NN    100000
#define NE    1200000
#define F_IN  64
#define F_HID 16
#define F_OUT 40

#define SCAN_BS 1024
#define NBLK    ((NN + SCAN_BS - 1) / SCAN_BS)   // 98

// ---- scratch (static device globals; referenced ONLY from device code) ----
// INVARIANT: g_cnt is all-zero at entry of every kernel_launch call:
//   zero-initialized at module load, and re-zeroed by k_out at the end of
//   every call (after its last use).
__device__ float g_xs  [NN * F_HID];   // x @ W1_self + b1
__device__ float g_xn  [NN * F_HID];   // x @ W1_neigh
__device__ float g_h   [NN * F_HID];   // hidden activations
__device__ float g_agg2[NN * F_HID];   // layer-2 neighbor sums
__device__ int   g_cnt [NN];           // in-degree (see invariant above)
__device__ int   g_off [NN];           // within-block offsets; scatter bumps to within-block END
__device__ int   g_eidx[NE];           // src ids bucketed by dst
__device__ int   g_bsum[128];          // scan block totals
__device__ int   g_bexc[128];          // published exclusive prefix of g_bsum (by k_scatter blk 0)

// Warp 0 computes the 98-entry exclusive prefix of g_bsum into shared sexc[].
// Call with threadIdx.x < 32 only; caller must __syncthreads afterwards.
__device__ __forceinline__ void block_base_scan(int* sexc)
{
    const unsigned FULL = 0xffffffffu;
    int tid = threadIdx.x;
    int base = 0;
#pragma unroll
    for (int c = 0; c < 4; c++) {
        int idx = c * 32 + tid;
        int v = (idx < NBLK) ? g_bsum[idx] : 0;
        int sc = v;
#pragma unroll
        for (int o = 1; o < 32; o <<= 1) {
            int t = __shfl_up_sync(FULL, sc, o);
            if (tid >= o) sc += t;
        }
        sexc[idx] = base + sc - v;                 // exclusive prefix
        base += __shfl_sync(FULL, sc, 31);
    }
}

// ---------------------------------------------------------------------------
// Kernel 1: fused layer-1 projections + dst-degree histogram.
// Grid covers all E edges; the first ceil(N/256) blocks also run the GEMM.
// ---------------------------------------------------------------------------
__global__ __launch_bounds__(256)
void k_lin1c(const float* __restrict__ x,
             const int*   __restrict__ ei,
             const float* __restrict__ W1s,
             const float* __restrict__ W1n,
             const float* __restrict__ b1,
             int n, int e)
{
    int t = blockIdx.x * blockDim.x + threadIdx.x;

    // degree histogram (all blocks; g_cnt starts at zero by invariant)
    if (t < e) {
        int dst = __ldg(ei + e + t);
        atomicAdd(g_cnt + dst, 1);
    }

    // node GEMM (block-uniform early-out for pure-histogram blocks)
    if (blockIdx.x * blockDim.x >= (unsigned)n) return;

    __shared__ float4 sWs[F_IN * (F_HID / 4)];   // [k][jb]
    __shared__ float4 sWn[F_IN * (F_HID / 4)];
    for (int i = threadIdx.x; i < F_IN * F_HID; i += blockDim.x) {
        ((float*)sWs)[i] = W1s[i];
        ((float*)sWn)[i] = W1n[i];
    }
    __syncthreads();

    int node = t;
    if (node >= n) return;

    float4 z = make_float4(0.f, 0.f, 0.f, 0.f);
    float4 accS[4], accN[4];
    const float4* b1v = (const float4*)b1;
#pragma unroll
    for (int jb = 0; jb < 4; jb++) { accS[jb] = __ldg(b1v + jb); accN[jb] = z; }

    const float4* xrow = (const float4*)x + node * (F_IN / 4);
#pragma unroll 1
    for (int kb = 0; kb < F_IN / 4; kb++) {
        float4 xv = __ldg(xrow + kb);
        float xk[4] = { xv.x, xv.y, xv.z, xv.w };
#pragma unroll
        for (int kk = 0; kk < 4; kk++) {
            int k = kb * 4 + kk;
            float xs = xk[kk];
#pragma unroll
            for (int jb = 0; jb < 4; jb++) {
                float4 ws = sWs[k * 4 + jb];
                float4 wn = sWn[k * 4 + jb];
                accS[jb].x += xs * ws.x; accS[jb].y += xs * ws.y;
                accS[jb].z += xs * ws.z; accS[jb].w += xs * ws.w;
                accN[jb].x += xs * wn.x; accN[jb].y += xs * wn.y;
                accN[jb].z += xs * wn.z; accN[jb].w += xs * wn.w;
            }
        }
    }

    float4* xsrow = (float4*)g_xs + node * 4;
    float4* xnrow = (float4*)g_xn + node * 4;
#pragma unroll
    for (int jb = 0; jb < 4; jb++) { xsrow[jb] = accS[jb]; xnrow[jb] = accN[jb]; }
}

// ---------------------------------------------------------------------------
// Kernel 2: per-block scan -> exclusive-within-block offsets + block totals
// ---------------------------------------------------------------------------
__global__ __launch_bounds__(SCAN_BS)
void k_scan1()
{
    __shared__ int s[SCAN_BS];
    int i = blockIdx.x * SCAN_BS + threadIdx.x;
    int v = (i < NN) ? g_cnt[i] : 0;
    s[threadIdx.x] = v;
    __syncthreads();
#pragma unroll
    for (int off = 1; off < SCAN_BS; off <<= 1) {
        int t = (threadIdx.x >= off) ? s[threadIdx.x - off] : 0;
        __syncthreads();
        s[threadIdx.x] += t;
        __syncthreads();
    }
    if (i < NN) g_off[i] = s[threadIdx.x] - v;          // exclusive within block
    if (threadIdx.x == SCAN_BS - 1) g_bsum[blockIdx.x] = s[SCAN_BS - 1];
}

// ---------------------------------------------------------------------------
// Kernel 3: scatter src ids into dst buckets (4 edges per thread).
// Each block recomputes the 98-entry base vector (cheap at 1172 blocks);
// block 0 additionally publishes it to g_bexc for the agg kernels.
// ---------------------------------------------------------------------------
__global__ __launch_bounds__(256)
void k_scatter(const int* __restrict__ ei, int e)
{
    __shared__ int sexc[128];
    if (threadIdx.x < 32) block_base_scan(sexc);
    __syncthreads();

    if (blockIdx.x == 0 && threadIdx.x < 128)
        g_bexc[threadIdx.x] = sexc[threadIdx.x];

    int e4 = e >> 2;
    int t = blockIdx.x * blockDim.x + threadIdx.x;
    if (t < e4) {
        int4 s = __ldg((const int4*)ei + t);
        int4 d = __ldg((const int4*)(ei + e) + t);
        g_eidx[atomicAdd(g_off + d.x, 1) + sexc[d.x >> 10]] = s.x;
        g_eidx[atomicAdd(g_off + d.y, 1) + sexc[d.y >> 10]] = s.y;
        g_eidx[atomicAdd(g_off + d.z, 1) + sexc[d.z >> 10]] = s.z;
        g_eidx[atomicAdd(g_off + d.w, 1) + sexc[d.w >> 10]] = s.w;
    }
    if (t == 0) {   // tail (e % 4 edges)
        for (int i = e4 * 4; i < e; i++) {
            int s = __ldg(ei + i);
            int d = __ldg(ei + e + i);
            g_eidx[atomicAdd(g_off + d, 1) + sexc[d >> 10]] = s;
        }
    }
}

// ---------------------------------------------------------------------------
// Warp-gather core: sums feat rows (16 floats each) of the neighbors of
// `node` into a per-lane partial (reduced across nb afterwards).
// Fast path: up to 32 neighbor ids preloaded in ONE parallel round and
// distributed by shuffle, so row loads don't wait on serial eidx loads.
// Lane layout: nb = lane>>2 (8 row slots), jb = lane&3 (float4 column).
// ---------------------------------------------------------------------------
__device__ __forceinline__ float4 warp_gather_sum(const float4* __restrict__ feat,
                                                  int beg, int end,
                                                  int lane, int nb, int jb)
{
    const unsigned FULL = 0xffffffffu;
    float4 acc = make_float4(0.f, 0.f, 0.f, 0.f);

    int deg = end - beg;
    int deg32 = deg < 32 ? deg : 32;

    // one parallel round: lane i holds eidx[beg+i]
    int nidx = (lane < deg32) ? g_eidx[beg + lane] : 0;

    int trips = (deg32 + 7) >> 3;            // warp-uniform
    for (int tIt = 0; tIt < trips; tIt++) {
        int j = nb + (tIt << 3);
        int s = __shfl_sync(FULL, nidx, j & 31);
        if (j < deg32) {
            float4 v = feat[s * 4 + jb];
            acc.x += v.x; acc.y += v.y; acc.z += v.z; acc.w += v.w;
        }
    }
    // rare slow path: neighbors beyond 32
    for (int i = beg + 32 + nb; i < end; i += 8) {
        int s = g_eidx[i];
        float4 v = feat[s * 4 + jb];
        acc.x += v.x; acc.y += v.y; acc.z += v.z; acc.w += v.w;
    }

    // reduce across the 8 row slots (lanes with same jb)
#pragma unroll
    for (int off = 4; off < 32; off <<= 1) {
        acc.x += __shfl_xor_sync(FULL, acc.x, off);
        acc.y += __shfl_xor_sync(FULL, acc.y, off);
        acc.z += __shfl_xor_sync(FULL, acc.z, off);
        acc.w += __shfl_xor_sync(FULL, acc.w, off);
    }
    return acc;
}

// ---------------------------------------------------------------------------
// Kernel 4: layer-1 aggregation (warp per node) + hidden activation:
//   h = relu(xs + mean_neigh(xn))
// ---------------------------------------------------------------------------
__global__ __launch_bounds__(256)
void k_agg1(int n)
{
    int warp = (blockIdx.x * blockDim.x + threadIdx.x) >> 5;
    if (warp >= n) return;
    int lane = threadIdx.x & 31;
    int nb = lane >> 2;
    int jb = lane & 3;

    int deg = g_cnt[warp];
    int end = g_off[warp] + __ldg(&g_bexc[warp >> 10]);   // global end offset
    int beg = end - deg;

    float4 acc = warp_gather_sum((const float4*)g_xn, beg, end, lane, nb, jb);

    if (nb == 0) {
        float invd = 1.0f / fmaxf((float)deg, 1.0f);
        float4 sv = ((const float4*)g_xs)[warp * 4 + jb];
        float4 r;
        r.x = fmaxf(sv.x + acc.x * invd, 0.f);
        r.y = fmaxf(sv.y + acc.y * invd, 0.f);
        r.z = fmaxf(sv.z + acc.z * invd, 0.f);
        r.w = fmaxf(sv.w + acc.w * invd, 0.f);
        ((float4*)g_h)[warp * 4 + jb] = r;
    }
}

// ---------------------------------------------------------------------------
// Kernel 5: layer-2 aggregation (warp per node): agg2 = sum_neigh(h)
// ---------------------------------------------------------------------------
__global__ __launch_bounds__(256)
void k_agg2(int n)
{
    int warp = (blockIdx.x * blockDim.x + threadIdx.x) >> 5;
    if (warp >= n) return;
    int lane = threadIdx.x & 31;
    int nb = lane >> 2;
    int jb = lane & 3;

    int end = g_off[warp] + __ldg(&g_bexc[warp >> 10]);
    int beg = end - g_cnt[warp];

    float4 acc = warp_gather_sum((const float4*)g_h, beg, end, lane, nb, jb);

    if (nb == 0) ((float4*)g_agg2)[warp * 4 + jb] = acc;
}

// ---------------------------------------------------------------------------
// Kernel 6: out = log_softmax(h @ W2s + (agg2/deg) @ W2n + b2)
// Also re-zeroes g_cnt (restores the entry invariant for the next call).
// ---------------------------------------------------------------------------
__global__ __launch_bounds__(256)
void k_out(const float* __restrict__ W2s,
           const float* __restrict__ W2n,
           const float* __restrict__ b2,
           float* __restrict__ out,
           int n)
{
    __shared__ float4 sWs[F_HID * (F_OUT / 4)];
    __shared__ float4 sWn[F_HID * (F_OUT / 4)];
    __shared__ float4 sb[F_OUT / 4];
    for (int i = threadIdx.x; i < F_HID * F_OUT; i += blockDim.x) {
        ((float*)sWs)[i] = W2s[i];
        ((float*)sWn)[i] = W2n[i];
    }
    for (int i = threadIdx.x; i < F_OUT; i += blockDim.x) ((float*)sb)[i] = b2[i];
    __syncthreads();

    int node = blockIdx.x * blockDim.x + threadIdx.x;
    if (node >= n) return;

    float invd = 1.0f / fmaxf((float)g_cnt[node], 1.0f);
    g_cnt[node] = 0;    // restore invariant (last use of cnt this call)

    float hk[F_HID], ak[F_HID];
    const float4* hrow = (const float4*)g_h    + node * 4;
    const float4* arow = (const float4*)g_agg2 + node * 4;
#pragma unroll
    for (int jb = 0; jb < 4; jb++) {
        float4 hv = hrow[jb];
        float4 av = arow[jb];
        hk[jb*4+0] = hv.x; hk[jb*4+1] = hv.y; hk[jb*4+2] = hv.z; hk[jb*4+3] = hv.w;
        ak[jb*4+0] = av.x * invd; ak[jb*4+1] = av.y * invd;
        ak[jb*4+2] = av.z * invd; ak[jb*4+3] = av.w * invd;
    }

    float4 acc[F_OUT / 4];
#pragma unroll
    for (int jb = 0; jb < F_OUT / 4; jb++) acc[jb] = sb[jb];

#pragma unroll
    for (int k = 0; k < F_HID; k++) {
        float hv = hk[k], av = ak[k];
#pragma unroll
        for (int jb = 0; jb < F_OUT / 4; jb++) {
            float4 ws = sWs[k * (F_OUT / 4) + jb];
            float4 wn = sWn[k * (F_OUT / 4) + jb];
            acc[jb].x += hv * ws.x + av * wn.x;
            acc[jb].y += hv * ws.y + av * wn.y;
            acc[jb].z += hv * ws.z + av * wn.z;
            acc[jb].w += hv * ws.w + av * wn.w;
        }
    }

    float m = -1e30f;
#pragma unroll
    for (int jb = 0; jb < F_OUT / 4; jb++) {
        m = fmaxf(m, fmaxf(fmaxf(acc[jb].x, acc[jb].y), fmaxf(acc[jb].z, acc[jb].w)));
    }
    float ssum = 0.f;
#pragma unroll
    for (int jb = 0; jb < F_OUT / 4; jb++) {
        ssum += expf(acc[jb].x - m) + expf(acc[jb].y - m)
              + expf(acc[jb].z - m) + expf(acc[jb].w - m);
    }
    float lse = m + logf(ssum);

    float4* orow = (float4*)(out + (size_t)node * F_OUT);
#pragma unroll
    for (int jb = 0; jb < F_OUT / 4; jb++) {
        float4 r;
        r.x = acc[jb].x - lse; r.y = acc[jb].y - lse;
        r.z = acc[jb].z - lse; r.w = acc[jb].w - lse;
        orow[jb] = r;
    }
}

// ---------------------------------------------------------------------------
extern "C" void kernel_launch(void* const* d_in, const int* in_sizes, int n_in,
                              void* d_out, int out_size)
{
    const float* x   = (const float*)d_in[0];
    const int*   ei  = (const int*)  d_in[1];
    const float* W1s = (const float*)d_in[2];
    const float* W1n = (const float*)d_in[3];
    const float* b1  = (const float*)d_in[4];
    const float* W2s = (const float*)d_in[5];
    const float* W2n = (const float*)d_in[6];
    const float* b2  = (const float*)d_in[7];
    float* out = (float*)d_out;

    int n = in_sizes[0] / F_IN;   // 100000
    int e = in_sizes[1] / 2;      // 1200000

    const int TB = 256;
    int nb_node = (n + TB - 1) / TB;
    int nb_edge = (e + TB - 1) / TB;
    int nb_sct  = ((e >> 2) + TB - 1) / TB;
    int nb_warp = (n * 32 + TB - 1) / TB;   // warp-per-node kernels

    k_lin1c  <<<nb_edge, TB>>>(x, ei, W1s, W1n, b1, n, e);
    k_scan1  <<<NBLK, SCAN_BS>>>();
    k_scatter<<<nb_sct, TB>>>(ei, e);
    k_agg1   <<<nb_warp, TB>>>(n);
    k_agg2   <<<nb_warp, TB>>>(n);
    k_out    <<<nb_node, TB>>>(W2s, W2n, b2, out, n);
}

// round 14
// speedup vs baseline: 1.1631x; 1.1631x over previous
#include <cuda_runtime.h>
#include <math.h>

#define NN    100000
#define NE    1200000
#define F_IN  64
#define F_HID 16
#define F_OUT 40

#define SCAN_BS 1024
#define NBLK    ((NN + SCAN_BS - 1) / SCAN_BS)   // 98

// ---- scratch (static device globals; referenced ONLY from device code) ----
// INVARIANT: g_cnt is all-zero at entry of every kernel_launch call:
//   zero-initialized at module load, and re-zeroed by k_out at the end of
//   every call (after its last use).
__device__ float g_xs  [NN * F_HID];   // x @ W1_self + b1
__device__ float g_xn  [NN * F_HID];   // x @ W1_neigh
__device__ float g_h   [NN * F_HID];   // hidden activations
__device__ float g_agg2[NN * F_HID];   // layer-2 neighbor sums
__device__ int   g_cnt [NN];           // in-degree (see invariant above)
__device__ int   g_off [NN];           // within-block offsets; scatter bumps to within-block END
__device__ int   g_eidx[NE];           // src ids bucketed by dst
__device__ int   g_bsum[128];          // scan block totals
__device__ int   g_bexc[128];          // published exclusive prefix of g_bsum (by k_scatter blk 0)

// Warp 0 computes the 98-entry exclusive prefix of g_bsum into shared sexc[].
// Call with threadIdx.x < 32 only; caller must __syncthreads afterwards.
__device__ __forceinline__ void block_base_scan(int* sexc)
{
    const unsigned FULL = 0xffffffffu;
    int tid = threadIdx.x;
    int base = 0;
#pragma unroll
    for (int c = 0; c < 4; c++) {
        int idx = c * 32 + tid;
        int v = (idx < NBLK) ? g_bsum[idx] : 0;
        int sc = v;
#pragma unroll
        for (int o = 1; o < 32; o <<= 1) {
            int t = __shfl_up_sync(FULL, sc, o);
            if (tid >= o) sc += t;
        }
        sexc[idx] = base + sc - v;                 // exclusive prefix
        base += __shfl_sync(FULL, sc, 31);
    }
}

// ---------------------------------------------------------------------------
// Kernel 1: fused layer-1 projections + dst-degree histogram.
// Grid covers all E edges; the first ceil(N/256) blocks also run the GEMM.
// ---------------------------------------------------------------------------
__global__ __launch_bounds__(256)
void k_lin1c(const float* __restrict__ x,
             const int*   __restrict__ ei,
             const float* __restrict__ W1s,
             const float* __restrict__ W1n,
             const float* __restrict__ b1,
             int n, int e)
{
    int t = blockIdx.x * blockDim.x + threadIdx.x;

    // degree histogram (all blocks; g_cnt starts at zero by invariant)
    if (t < e) {
        int dst = __ldg(ei + e + t);
        atomicAdd(g_cnt + dst, 1);
    }

    // node GEMM (block-uniform early-out for pure-histogram blocks)
    if (blockIdx.x * blockDim.x >= (unsigned)n) return;

    __shared__ float4 sWs[F_IN * (F_HID / 4)];   // [k][jb]
    __shared__ float4 sWn[F_IN * (F_HID / 4)];
    for (int i = threadIdx.x; i < F_IN * F_HID; i += blockDim.x) {
        ((float*)sWs)[i] = W1s[i];
        ((float*)sWn)[i] = W1n[i];
    }
    __syncthreads();

    int node = t;
    if (node >= n) return;

    float4 z = make_float4(0.f, 0.f, 0.f, 0.f);
    float4 accS[4], accN[4];
    const float4* b1v = (const float4*)b1;
#pragma unroll
    for (int jb = 0; jb < 4; jb++) { accS[jb] = __ldg(b1v + jb); accN[jb] = z; }

    const float4* xrow = (const float4*)x + node * (F_IN / 4);
#pragma unroll 1
    for (int kb = 0; kb < F_IN / 4; kb++) {
        float4 xv = __ldg(xrow + kb);
        float xk[4] = { xv.x, xv.y, xv.z, xv.w };
#pragma unroll
        for (int kk = 0; kk < 4; kk++) {
            int k = kb * 4 + kk;
            float xs = xk[kk];
#pragma unroll
            for (int jb = 0; jb < 4; jb++) {
                float4 ws = sWs[k * 4 + jb];
                float4 wn = sWn[k * 4 + jb];
                accS[jb].x += xs * ws.x; accS[jb].y += xs * ws.y;
                accS[jb].z += xs * ws.z; accS[jb].w += xs * ws.w;
                accN[jb].x += xs * wn.x; accN[jb].y += xs * wn.y;
                accN[jb].z += xs * wn.z; accN[jb].w += xs * wn.w;
            }
        }
    }

    float4* xsrow = (float4*)g_xs + node * 4;
    float4* xnrow = (float4*)g_xn + node * 4;
#pragma unroll
    for (int jb = 0; jb < 4; jb++) { xsrow[jb] = accS[jb]; xnrow[jb] = accN[jb]; }
}

// ---------------------------------------------------------------------------
// Kernel 2: per-block scan -> exclusive-within-block offsets + block totals
// ---------------------------------------------------------------------------
__global__ __launch_bounds__(SCAN_BS)
void k_scan1()
{
    __shared__ int s[SCAN_BS];
    int i = blockIdx.x * SCAN_BS + threadIdx.x;
    int v = (i < NN) ? g_cnt[i] : 0;
    s[threadIdx.x] = v;
    __syncthreads();
#pragma unroll
    for (int off = 1; off < SCAN_BS; off <<= 1) {
        int t = (threadIdx.x >= off) ? s[threadIdx.x - off] : 0;
        __syncthreads();
        s[threadIdx.x] += t;
        __syncthreads();
    }
    if (i < NN) g_off[i] = s[threadIdx.x] - v;          // exclusive within block
    if (threadIdx.x == SCAN_BS - 1) g_bsum[blockIdx.x] = s[SCAN_BS - 1];
}

// ---------------------------------------------------------------------------
// Kernel 3: scatter src ids into dst buckets (4 edges per thread).
// Each block recomputes the 98-entry base vector (cheap at 1172 blocks);
// block 0 additionally publishes it to g_bexc for the agg kernels.
// ---------------------------------------------------------------------------
__global__ __launch_bounds__(256)
void k_scatter(const int* __restrict__ ei, int e)
{
    __shared__ int sexc[128];
    if (threadIdx.x < 32) block_base_scan(sexc);
    __syncthreads();

    if (blockIdx.x == 0 && threadIdx.x < 128)
        g_bexc[threadIdx.x] = sexc[threadIdx.x];

    int e4 = e >> 2;
    int t = blockIdx.x * blockDim.x + threadIdx.x;
    if (t < e4) {
        int4 s = __ldg((const int4*)ei + t);
        int4 d = __ldg((const int4*)(ei + e) + t);
        g_eidx[atomicAdd(g_off + d.x, 1) + sexc[d.x >> 10]] = s.x;
        g_eidx[atomicAdd(g_off + d.y, 1) + sexc[d.y >> 10]] = s.y;
        g_eidx[atomicAdd(g_off + d.z, 1) + sexc[d.z >> 10]] = s.z;
        g_eidx[atomicAdd(g_off + d.w, 1) + sexc[d.w >> 10]] = s.w;
    }
    if (t == 0) {   // tail (e % 4 edges)
        for (int i = e4 * 4; i < e; i++) {
            int s = __ldg(ei + i);
            int d = __ldg(ei + e + i);
            g_eidx[atomicAdd(g_off + d, 1) + sexc[d >> 10]] = s;
        }
    }
}

// ---------------------------------------------------------------------------
// Kernel 4: layer-1 aggregation, TWO nodes per warp, + hidden activation:
//   h = relu(xs + mean_neigh(xn))
// Lanes 0-15 -> node 2w, lanes 16-31 -> node 2w+1.
// Within a half: nb = 4 row slots, jb = float4 column.
// ---------------------------------------------------------------------------
__global__ __launch_bounds__(256)
void k_agg1(int n)
{
    const unsigned FULL = 0xffffffffu;
    int warp = (blockIdx.x * blockDim.x + threadIdx.x) >> 5;
    int lane = threadIdx.x & 31;
    int half = lane >> 4;            // 0 or 1
    int l    = lane & 15;
    int nb   = l >> 2;               // 4 row slots
    int jb   = l & 3;                // float4 column

    int node = warp * 2 + half;
    if (warp * 2 >= n) return;       // whole warp out of range

    int deg = 0, beg = 0, end = 0;
    if (node < n) {
        deg = g_cnt[node];
        end = g_off[node] + __ldg(&g_bexc[node >> 10]);
        beg = end - deg;
    }

    float4 acc = make_float4(0.f, 0.f, 0.f, 0.f);
    for (int i = beg + nb; i < end; i += 4) {
        int s = g_eidx[i];
        float4 v = ((const float4*)g_xn)[s * 4 + jb];
        acc.x += v.x; acc.y += v.y; acc.z += v.z; acc.w += v.w;
    }
    // reduce across the 4 row slots (xor 4, 8 stays within the 16-lane half)
#pragma unroll
    for (int off = 4; off < 16; off <<= 1) {
        acc.x += __shfl_xor_sync(FULL, acc.x, off);
        acc.y += __shfl_xor_sync(FULL, acc.y, off);
        acc.z += __shfl_xor_sync(FULL, acc.z, off);
        acc.w += __shfl_xor_sync(FULL, acc.w, off);
    }

    if (nb == 0 && node < n) {
        float invd = 1.0f / fmaxf((float)deg, 1.0f);
        float4 sv = ((const float4*)g_xs)[node * 4 + jb];
        float4 r;
        r.x = fmaxf(sv.x + acc.x * invd, 0.f);
        r.y = fmaxf(sv.y + acc.y * invd, 0.f);
        r.z = fmaxf(sv.z + acc.z * invd, 0.f);
        r.w = fmaxf(sv.w + acc.w * invd, 0.f);
        ((float4*)g_h)[node * 4 + jb] = r;
    }
}

// ---------------------------------------------------------------------------
// Kernel 5: layer-2 aggregation, TWO nodes per warp: agg2 = sum_neigh(h)
// ---------------------------------------------------------------------------
__global__ __launch_bounds__(256)
void k_agg2(int n)
{
    const unsigned FULL = 0xffffffffu;
    int warp = (blockIdx.x * blockDim.x + threadIdx.x) >> 5;
    int lane = threadIdx.x & 31;
    int half = lane >> 4;
    int l    = lane & 15;
    int nb   = l >> 2;
    int jb   = l & 3;

    int node = warp * 2 + half;
    if (warp * 2 >= n) return;

    int beg = 0, end = 0;
    if (node < n) {
        end = g_off[node] + __ldg(&g_bexc[node >> 10]);
        beg = end - g_cnt[node];
    }

    float4 acc = make_float4(0.f, 0.f, 0.f, 0.f);
    for (int i = beg + nb; i < end; i += 4) {
        int s = g_eidx[i];
        float4 v = ((const float4*)g_h)[s * 4 + jb];
        acc.x += v.x; acc.y += v.y; acc.z += v.z; acc.w += v.w;
    }
#pragma unroll
    for (int off = 4; off < 16; off <<= 1) {
        acc.x += __shfl_xor_sync(FULL, acc.x, off);
        acc.y += __shfl_xor_sync(FULL, acc.y, off);
        acc.z += __shfl_xor_sync(FULL, acc.z, off);
        acc.w += __shfl_xor_sync(FULL, acc.w, off);
    }
    if (nb == 0 && node < n)
        ((float4*)g_agg2)[node * 4 + jb] = acc;
}

// ---------------------------------------------------------------------------
// Kernel 6: out = log_softmax(h @ W2s + (agg2/deg) @ W2n + b2)
// Also re-zeroes g_cnt (restores the entry invariant for the next call).
// ---------------------------------------------------------------------------
__global__ __launch_bounds__(256)
void k_out(const float* __restrict__ W2s,
           const float* __restrict__ W2n,
           const float* __restrict__ b2,
           float* __restrict__ out,
           int n)
{
    __shared__ float4 sWs[F_HID * (F_OUT / 4)];
    __shared__ float4 sWn[F_HID * (F_OUT / 4)];
    __shared__ float4 sb[F_OUT / 4];
    for (int i = threadIdx.x; i < F_HID * F_OUT; i += blockDim.x) {
        ((float*)sWs)[i] = W2s[i];
        ((float*)sWn)[i] = W2n[i];
    }
    for (int i = threadIdx.x; i < F_OUT; i += blockDim.x) ((float*)sb)[i] = b2[i];
    __syncthreads();

    int node = blockIdx.x * blockDim.x + threadIdx.x;
    if (node >= n) return;

    float invd = 1.0f / fmaxf((float)g_cnt[node], 1.0f);
    g_cnt[node] = 0;    // restore invariant (last use of cnt this call)

    float hk[F_HID], ak[F_HID];
    const float4* hrow = (const float4*)g_h    + node * 4;
    const float4* arow = (const float4*)g_agg2 + node * 4;
#pragma unroll
    for (int jb = 0; jb < 4; jb++) {
        float4 hv = hrow[jb];
        float4 av = arow[jb];
        hk[jb*4+0] = hv.x; hk[jb*4+1] = hv.y; hk[jb*4+2] = hv.z; hk[jb*4+3] = hv.w;
        ak[jb*4+0] = av.x * invd; ak[jb*4+1] = av.y * invd;
        ak[jb*4+2] = av.z * invd; ak[jb*4+3] = av.w * invd;
    }

    float4 acc[F_OUT / 4];
#pragma unroll
    for (int jb = 0; jb < F_OUT / 4; jb++) acc[jb] = sb[jb];

#pragma unroll
    for (int k = 0; k < F_HID; k++) {
        float hv = hk[k], av = ak[k];
#pragma unroll
        for (int jb = 0; jb < F_OUT / 4; jb++) {
            float4 ws = sWs[k * (F_OUT / 4) + jb];
            float4 wn = sWn[k * (F_OUT / 4) + jb];
            acc[jb].x += hv * ws.x + av * wn.x;
            acc[jb].y += hv * ws.y + av * wn.y;
            acc[jb].z += hv * ws.z + av * wn.z;
            acc[jb].w += hv * ws.w + av * wn.w;
        }
    }

    float m = -1e30f;
#pragma unroll
    for (int jb = 0; jb < F_OUT / 4; jb++) {
        m = fmaxf(m, fmaxf(fmaxf(acc[jb].x, acc[jb].y), fmaxf(acc[jb].z, acc[jb].w)));
    }
    float ssum = 0.f;
#pragma unroll
    for (int jb = 0; jb < F_OUT / 4; jb++) {
        ssum += expf(acc[jb].x - m) + expf(acc[jb].y - m)
              + expf(acc[jb].z - m) + expf(acc[jb].w - m);
    }
    float lse = m + logf(ssum);

    float4* orow = (float4*)(out + (size_t)node * F_OUT);
#pragma unroll
    for (int jb = 0; jb < F_OUT / 4; jb++) {
        float4 r;
        r.x = acc[jb].x - lse; r.y = acc[jb].y - lse;
        r.z = acc[jb].z - lse; r.w = acc[jb].w - lse;
        orow[jb] = r;
    }
}

// ---------------------------------------------------------------------------
extern "C" void kernel_launch(void* const* d_in, const int* in_sizes, int n_in,
                              void* d_out, int out_size)
{
    const float* x   = (const float*)d_in[0];
    const int*   ei  = (const int*)  d_in[1];
    const float* W1s = (const float*)d_in[2];
    const float* W1n = (const float*)d_in[3];
    const float* b1  = (const float*)d_in[4];
    const float* W2s = (const float*)d_in[5];
    const float* W2n = (const float*)d_in[6];
    const float* b2  = (const float*)d_in[7];
    float* out = (float*)d_out;

    int n = in_sizes[0] / F_IN;   // 100000
    int e = in_sizes[1] / 2;      // 1200000

    const int TB = 256;
    int nb_node = (n + TB - 1) / TB;
    int nb_edge = (e + TB - 1) / TB;
    int nb_sct  = ((e >> 2) + TB - 1) / TB;
    int nwarp2  = (n + 1) / 2;                       // 2 nodes per warp
    int nb_warp = (nwarp2 * 32 + TB - 1) / TB;

    k_lin1c  <<<nb_edge, TB>>>(x, ei, W1s, W1n, b1, n, e);
    k_scan1  <<<NBLK, SCAN_BS>>>();
    k_scatter<<<nb_sct, TB>>>(ei, e);
    k_agg1   <<<nb_warp, TB>>>(n);
    k_agg2   <<<nb_warp, TB>>>(n);
    k_out    <<<nb_node, TB>>>(W2s, W2n, b2, out, n);
}

// round 15
// speedup vs baseline: 1.1927x; 1.0255x over previous
#include <cuda_runtime.h>
#include <math.h>

#define NN    100000
#define NE    1200000
#define F_IN  64
#define F_HID 16
#define F_OUT 40

#define SCAN_BS 1024
#define NBLK    ((NN + SCAN_BS - 1) / SCAN_BS)   // 98

// ---- scratch (static device globals; referenced ONLY from device code) ----
// INVARIANT: g_cnt is all-zero at entry of every kernel_launch call:
//   zero-initialized at module load, and re-zeroed by k_out at the end of
//   every call (after its last use).
__device__ float g_xs  [NN * F_HID];   // x @ W1_self + b1
__device__ float g_xn  [NN * F_HID];   // x @ W1_neigh
__device__ float g_h   [NN * F_HID];   // hidden activations
__device__ float g_agg2[NN * F_HID];   // layer-2 neighbor sums
__device__ int   g_cnt [NN];           // in-degree (see invariant above)
__device__ int   g_off [NN];           // within-block offsets; scatter bumps to within-block END
__device__ int   g_eidx[NE];           // src ids bucketed by dst
__device__ int   g_bsum[128];          // scan block totals
__device__ int   g_bexc[128];          // published exclusive prefix of g_bsum (by k_scatter blk 0)

// Warp 0 computes the 98-entry exclusive prefix of g_bsum into shared sexc[].
// Call with threadIdx.x < 32 only; caller must __syncthreads afterwards.
__device__ __forceinline__ void block_base_scan(int* sexc)
{
    const unsigned FULL = 0xffffffffu;
    int tid = threadIdx.x;
    int base = 0;
#pragma unroll
    for (int c = 0; c < 4; c++) {
        int idx = c * 32 + tid;
        int v = (idx < NBLK) ? g_bsum[idx] : 0;
        int sc = v;
#pragma unroll
        for (int o = 1; o < 32; o <<= 1) {
            int t = __shfl_up_sync(FULL, sc, o);
            if (tid >= o) sc += t;
        }
        sexc[idx] = base + sc - v;                 // exclusive prefix
        base += __shfl_sync(FULL, sc, 31);
    }
}

// ---------------------------------------------------------------------------
// Kernel 1: fused layer-1 projections + dst-degree histogram.
// Grid covers all E edges; the first ceil(N/256) blocks also run the GEMM.
// ---------------------------------------------------------------------------
__global__ __launch_bounds__(256)
void k_lin1c(const float* __restrict__ x,
             const int*   __restrict__ ei,
             const float* __restrict__ W1s,
             const float* __restrict__ W1n,
             const float* __restrict__ b1,
             int n, int e)
{
    int t = blockIdx.x * blockDim.x + threadIdx.x;

    // degree histogram (all blocks; g_cnt starts at zero by invariant)
    if (t < e) {
        int dst = __ldg(ei + e + t);
        atomicAdd(g_cnt + dst, 1);
    }

    // node GEMM (block-uniform early-out for pure-histogram blocks)
    if (blockIdx.x * blockDim.x >= (unsigned)n) return;

    __shared__ float4 sWs[F_IN * (F_HID / 4)];   // [k][jb]
    __shared__ float4 sWn[F_IN * (F_HID / 4)];
    for (int i = threadIdx.x; i < F_IN * F_HID; i += blockDim.x) {
        ((float*)sWs)[i] = W1s[i];
        ((float*)sWn)[i] = W1n[i];
    }
    __syncthreads();

    int node = t;
    if (node >= n) return;

    float4 z = make_float4(0.f, 0.f, 0.f, 0.f);
    float4 accS[4], accN[4];
    const float4* b1v = (const float4*)b1;
#pragma unroll
    for (int jb = 0; jb < 4; jb++) { accS[jb] = __ldg(b1v + jb); accN[jb] = z; }

    const float4* xrow = (const float4*)x + node * (F_IN / 4);
#pragma unroll 1
    for (int kb = 0; kb < F_IN / 4; kb++) {
        float4 xv = __ldg(xrow + kb);
        float xk[4] = { xv.x, xv.y, xv.z, xv.w };
#pragma unroll
        for (int kk = 0; kk < 4; kk++) {
            int k = kb * 4 + kk;
            float xs = xk[kk];
#pragma unroll
            for (int jb = 0; jb < 4; jb++) {
                float4 ws = sWs[k * 4 + jb];
                float4 wn = sWn[k * 4 + jb];
                accS[jb].x += xs * ws.x; accS[jb].y += xs * ws.y;
                accS[jb].z += xs * ws.z; accS[jb].w += xs * ws.w;
                accN[jb].x += xs * wn.x; accN[jb].y += xs * wn.y;
                accN[jb].z += xs * wn.z; accN[jb].w += xs * wn.w;
            }
        }
    }

    float4* xsrow = (float4*)g_xs + node * 4;
    float4* xnrow = (float4*)g_xn + node * 4;
#pragma unroll
    for (int jb = 0; jb < 4; jb++) { xsrow[jb] = accS[jb]; xnrow[jb] = accN[jb]; }
}

// ---------------------------------------------------------------------------
// Kernel 2: per-block scan -> exclusive-within-block offsets + block totals
// ---------------------------------------------------------------------------
__global__ __launch_bounds__(SCAN_BS)
void k_scan1()
{
    __shared__ int s[SCAN_BS];
    int i = blockIdx.x * SCAN_BS + threadIdx.x;
    int v = (i < NN) ? g_cnt[i] : 0;
    s[threadIdx.x] = v;
    __syncthreads();
#pragma unroll
    for (int off = 1; off < SCAN_BS; off <<= 1) {
        int t = (threadIdx.x >= off) ? s[threadIdx.x - off] : 0;
        __syncthreads();
        s[threadIdx.x] += t;
        __syncthreads();
    }
    if (i < NN) g_off[i] = s[threadIdx.x] - v;          // exclusive within block
    if (threadIdx.x == SCAN_BS - 1) g_bsum[blockIdx.x] = s[SCAN_BS - 1];
}

// ---------------------------------------------------------------------------
// Kernel 3: scatter src ids into dst buckets (4 edges per thread).
// Each block recomputes the 98-entry base vector (cheap at 1172 blocks);
// block 0 additionally publishes it to g_bexc for the agg kernels.
// ---------------------------------------------------------------------------
__global__ __launch_bounds__(256)
void k_scatter(const int* __restrict__ ei, int e)
{
    __shared__ int sexc[128];
    if (threadIdx.x < 32) block_base_scan(sexc);
    __syncthreads();

    if (blockIdx.x == 0 && threadIdx.x < 128)
        g_bexc[threadIdx.x] = sexc[threadIdx.x];

    int e4 = e >> 2;
    int t = blockIdx.x * blockDim.x + threadIdx.x;
    if (t < e4) {
        int4 s = __ldg((const int4*)ei + t);
        int4 d = __ldg((const int4*)(ei + e) + t);
        g_eidx[atomicAdd(g_off + d.x, 1) + sexc[d.x >> 10]] = s.x;
        g_eidx[atomicAdd(g_off + d.y, 1) + sexc[d.y >> 10]] = s.y;
        g_eidx[atomicAdd(g_off + d.z, 1) + sexc[d.z >> 10]] = s.z;
        g_eidx[atomicAdd(g_off + d.w, 1) + sexc[d.w >> 10]] = s.w;
    }
    if (t == 0) {   // tail (e % 4 edges)
        for (int i = e4 * 4; i < e; i++) {
            int s = __ldg(ei + i);
            int d = __ldg(ei + e + i);
            g_eidx[atomicAdd(g_off + d, 1) + sexc[d >> 10]] = s;
        }
    }
}

// ---------------------------------------------------------------------------
// Kernel 4: layer-1 aggregation, FOUR nodes per warp, + hidden activation:
//   h = relu(xs + mean_neigh(xn))
// Lane layout: quarter = lane>>3 selects node 4w+quarter;
// within a quarter: nb = (lane>>2)&1 (2 row slots), jb = lane&3 (float4 col).
// ---------------------------------------------------------------------------
__global__ __launch_bounds__(256)
void k_agg1(int n)
{
    const unsigned FULL = 0xffffffffu;
    int warp = (blockIdx.x * blockDim.x + threadIdx.x) >> 5;
    int lane = threadIdx.x & 31;
    int quarter = lane >> 3;         // 0..3
    int nb = (lane >> 2) & 1;        // 2 row slots
    int jb = lane & 3;               // float4 column

    int node = warp * 4 + quarter;
    if (warp * 4 >= n) return;       // whole warp out of range

    int deg = 0, beg = 0, end = 0;
    if (node < n) {
        deg = g_cnt[node];
        end = g_off[node] + __ldg(&g_bexc[node >> 10]);
        beg = end - deg;
    }

    float4 acc = make_float4(0.f, 0.f, 0.f, 0.f);
    for (int i = beg + nb; i < end; i += 2) {
        int s = g_eidx[i];
        float4 v = ((const float4*)g_xn)[s * 4 + jb];
        acc.x += v.x; acc.y += v.y; acc.z += v.z; acc.w += v.w;
    }
    // reduce across the 2 row slots (xor 4 stays within the 8-lane quarter)
    acc.x += __shfl_xor_sync(FULL, acc.x, 4);
    acc.y += __shfl_xor_sync(FULL, acc.y, 4);
    acc.z += __shfl_xor_sync(FULL, acc.z, 4);
    acc.w += __shfl_xor_sync(FULL, acc.w, 4);

    if (nb == 0 && node < n) {
        float invd = 1.0f / fmaxf((float)deg, 1.0f);
        float4 sv = ((const float4*)g_xs)[node * 4 + jb];
        float4 r;
        r.x = fmaxf(sv.x + acc.x * invd, 0.f);
        r.y = fmaxf(sv.y + acc.y * invd, 0.f);
        r.z = fmaxf(sv.z + acc.z * invd, 0.f);
        r.w = fmaxf(sv.w + acc.w * invd, 0.f);
        ((float4*)g_h)[node * 4 + jb] = r;
    }
}

// ---------------------------------------------------------------------------
// Kernel 5: layer-2 aggregation, FOUR nodes per warp: agg2 = sum_neigh(h)
// ---------------------------------------------------------------------------
__global__ __launch_bounds__(256)
void k_agg2(int n)
{
    const unsigned FULL = 0xffffffffu;
    int warp = (blockIdx.x * blockDim.x + threadIdx.x) >> 5;
    int lane = threadIdx.x & 31;
    int quarter = lane >> 3;
    int nb = (lane >> 2) & 1;
    int jb = lane & 3;

    int node = warp * 4 + quarter;
    if (warp * 4 >= n) return;

    int beg = 0, end = 0;
    if (node < n) {
        end = g_off[node] + __ldg(&g_bexc[node >> 10]);
        beg = end - g_cnt[node];
    }

    float4 acc = make_float4(0.f, 0.f, 0.f, 0.f);
    for (int i = beg + nb; i < end; i += 2) {
        int s = g_eidx[i];
        float4 v = ((const float4*)g_h)[s * 4 + jb];
        acc.x += v.x; acc.y += v.y; acc.z += v.z; acc.w += v.w;
    }
    acc.x += __shfl_xor_sync(FULL, acc.x, 4);
    acc.y += __shfl_xor_sync(FULL, acc.y, 4);
    acc.z += __shfl_xor_sync(FULL, acc.z, 4);
    acc.w += __shfl_xor_sync(FULL, acc.w, 4);

    if (nb == 0 && node < n)
        ((float4*)g_agg2)[node * 4 + jb] = acc;
}

// ---------------------------------------------------------------------------
// Kernel 6: out = log_softmax(h @ W2s + (agg2/deg) @ W2n + b2)
// Also re-zeroes g_cnt (restores the entry invariant for the next call).
// ---------------------------------------------------------------------------
__global__ __launch_bounds__(256)
void k_out(const float* __restrict__ W2s,
           const float* __restrict__ W2n,
           const float* __restrict__ b2,
           float* __restrict__ out,
           int n)
{
    __shared__ float4 sWs[F_HID * (F_OUT / 4)];
    __shared__ float4 sWn[F_HID * (F_OUT / 4)];
    __shared__ float4 sb[F_OUT / 4];
    for (int i = threadIdx.x; i < F_HID * F_OUT; i += blockDim.x) {
        ((float*)sWs)[i] = W2s[i];
        ((float*)sWn)[i] = W2n[i];
    }
    for (int i = threadIdx.x; i < F_OUT; i += blockDim.x) ((float*)sb)[i] = b2[i];
    __syncthreads();

    int node = blockIdx.x * blockDim.x + threadIdx.x;
    if (node >= n) return;

    float invd = 1.0f / fmaxf((float)g_cnt[node], 1.0f);
    g_cnt[node] = 0;    // restore invariant (last use of cnt this call)

    float hk[F_HID], ak[F_HID];
    const float4* hrow = (const float4*)g_h    + node * 4;
    const float4* arow = (const float4*)g_agg2 + node * 4;
#pragma unroll
    for (int jb = 0; jb < 4; jb++) {
        float4 hv = hrow[jb];
        float4 av = arow[jb];
        hk[jb*4+0] = hv.x; hk[jb*4+1] = hv.y; hk[jb*4+2] = hv.z; hk[jb*4+3] = hv.w;
        ak[jb*4+0] = av.x * invd; ak[jb*4+1] = av.y * invd;
        ak[jb*4+2] = av.z * invd; ak[jb*4+3] = av.w * invd;
    }

    float4 acc[F_OUT / 4];
#pragma unroll
    for (int jb = 0; jb < F_OUT / 4; jb++) acc[jb] = sb[jb];

#pragma unroll
    for (int k = 0; k < F_HID; k++) {
        float hv = hk[k], av = ak[k];
#pragma unroll
        for (int jb = 0; jb < F_OUT / 4; jb++) {
            float4 ws = sWs[k * (F_OUT / 4) + jb];
            float4 wn = sWn[k * (F_OUT / 4) + jb];
            acc[jb].x += hv * ws.x + av * wn.x;
            acc[jb].y += hv * ws.y + av * wn.y;
            acc[jb].z += hv * ws.z + av * wn.z;
            acc[jb].w += hv * ws.w + av * wn.w;
        }
    }

    float m = -1e30f;
#pragma unroll
    for (int jb = 0; jb < F_OUT / 4; jb++) {
        m = fmaxf(m, fmaxf(fmaxf(acc[jb].x, acc[jb].y), fmaxf(acc[jb].z, acc[jb].w)));
    }
    float ssum = 0.f;
#pragma unroll
    for (int jb = 0; jb < F_OUT / 4; jb++) {
        ssum += expf(acc[jb].x - m) + expf(acc[jb].y - m)
              + expf(acc[jb].z - m) + expf(acc[jb].w - m);
    }
    float lse = m + logf(ssum);

    float4* orow = (float4*)(out + (size_t)node * F_OUT);
#pragma unroll
    for (int jb = 0; jb < F_OUT / 4; jb++) {
        float4 r;
        r.x = acc[jb].x - lse; r.y = acc[jb].y - lse;
        r.z = acc[jb].z - lse; r.w = acc[jb].w - lse;
        orow[jb] = r;
    }
}

// ---------------------------------------------------------------------------
extern "C" void kernel_launch(void* const* d_in, const int* in_sizes, int n_in,
                              void* d_out, int out_size)
{
    const float* x   = (const float*)d_in[0];
    const int*   ei  = (const int*)  d_in[1];
    const float* W1s = (const float*)d_in[2];
    const float* W1n = (const float*)d_in[3];
    const float* b1  = (const float*)d_in[4];
    const float* W2s = (const float*)d_in[5];
    const float* W2n = (const float*)d_in[6];
    const float* b2  = (const float*)d_in[7];
    float* out = (float*)d_out;

    int n = in_sizes[0] / F_IN;   // 100000
    int e = in_sizes[1] / 2;      // 1200000

    const int TB = 256;
    int nb_node = (n + TB - 1) / TB;
    int nb_edge = (e + TB - 1) / TB;
    int nb_sct  = ((e >> 2) + TB - 1) / TB;
    int nwarp4  = (n + 3) / 4;                       // 4 nodes per warp
    int nb_warp = (nwarp4 * 32 + TB - 1) / TB;

    k_lin1c  <<<nb_edge, TB>>>(x, ei, W1s, W1n, b1, n, e);
    k_scan1  <<<NBLK, SCAN_BS>>>();
    k_scatter<<<nb_sct, TB>>>(ei, e);
    k_agg1   <<<nb_warp, TB>>>(n);
    k_agg2   <<<nb_warp, TB>>>(n);
    k_out    <<<nb_node, TB>>>(W2s, W2n, b2, out, n);
}